// round 13
// baseline (speedup 1.0000x reference)
#include <cuda_runtime.h>
#include <cstdint>

// PoolingNms: MaxPool2d(k=3, stride=3) + MaxUnpool2d fused.
// x: [16, 1, 1536, 1536] fp32. Keep per-3x3-block first-argmax, zero rest.
//
// R13 = R12 (TMA bulk-async staging + vectorized patch compute) made into a
// per-CTA triple-buffered pipeline: each CTA owns 4 consecutive 18KB tiles;
// at every iteration the NEXT tile's bulk load is issued before computing the
// current one, and stores drain asynchronously (bulk_group, .read waits for
// buffer reuse only). The TMA queue never goes idle, removing the per-CTA
// load-latency head and store-drain tail that capped R12 at 76% DRAM.

static constexpr int W  = 1536;
static constexpr int H  = 1536;
static constexpr int BC = 16;
static constexpr int TROWS = 3;
static constexpr int TILE_FLOATS = TROWS * W;          // 4608
static constexpr int TILE_BYTES  = TILE_FLOATS * 4;    // 18432
static constexpr int NTHREADS = 128;                   // 1 thread = 1 patch
static constexpr int NTILES = BC * H / TROWS;          // 8192
static constexpr int TPC  = 4;
static constexpr int GRID = NTILES / TPC;              // 2048
static constexpr int NBUF = 3;
static constexpr int SMEM_TOTAL = NBUF * TILE_BYTES + NBUF * 8;  // 55320

__global__ __launch_bounds__(NTHREADS)
void pooling_nms_kernel(const float* __restrict__ x, float* __restrict__ out) {
    extern __shared__ __align__(128) char smem[];
    float* buf = reinterpret_cast<float*>(smem);
    const int tid = threadIdx.x;
    const size_t t0 = (size_t)blockIdx.x * TPC;

    uint32_t s_base;
    asm("{ .reg .u64 t; cvta.to.shared.u64 t, %1; cvt.u32.u64 %0, t; }"
        : "=r"(s_base) : "l"(smem));
    const uint32_t s_mbar0 = s_base + NBUF * TILE_BYTES;

    if (tid == 0) {
        #pragma unroll
        for (int q = 0; q < NBUF; q++)
            asm volatile("mbarrier.init.shared.b64 [%0], 1;"
                         :: "r"(s_mbar0 + q * 8) : "memory");
    }
    __syncthreads();

    // Prologue: load tile 0 into buf 0.
    if (tid == 0) {
        asm volatile("mbarrier.arrive.expect_tx.shared.b64 _, [%0], %1;"
                     :: "r"(s_mbar0), "r"((uint32_t)TILE_BYTES) : "memory");
        asm volatile(
            "{\n\t.reg .b64 pol;\n\t"
            "createpolicy.fractional.L2::evict_last.b64 pol, 1.0;\n\t"
            "cp.async.bulk.shared::cta.global.mbarrier::complete_tx::bytes.L2::cache_hint"
            " [%0], [%1], %2, [%3], pol;\n\t}"
            :: "r"(s_base), "l"(x + t0 * TILE_FLOATS),
               "r"((uint32_t)TILE_BYTES), "r"(s_mbar0) : "memory");
    }

    #pragma unroll
    for (int i = 0; i < TPC; i++) {
        const int p = i % NBUF;

        // Issue NEXT tile's load into buf[(i+1)%NBUF]. The store that last
        // used that buffer was committed a full iteration ago; allow the
        // most recent store to stay outstanding (.read 1).
        if (i + 1 < TPC && tid == 0) {
            const int pn = (i + 1) % NBUF;
            asm volatile("cp.async.bulk.wait_group.read 1;" ::: "memory");
            asm volatile("mbarrier.arrive.expect_tx.shared.b64 _, [%0], %1;"
                         :: "r"(s_mbar0 + pn * 8), "r"((uint32_t)TILE_BYTES)
                         : "memory");
            asm volatile(
                "{\n\t.reg .b64 pol;\n\t"
                "createpolicy.fractional.L2::evict_last.b64 pol, 1.0;\n\t"
                "cp.async.bulk.shared::cta.global.mbarrier::complete_tx::bytes.L2::cache_hint"
                " [%0], [%1], %2, [%3], pol;\n\t}"
                :: "r"(s_base + pn * TILE_BYTES),
                   "l"(x + (t0 + i + 1) * TILE_FLOATS),
                   "r"((uint32_t)TILE_BYTES), "r"(s_mbar0 + pn * 8) : "memory");
        }

        // Wait for tile i (parity = use index of this mbar).
        {
            const uint32_t mb = s_mbar0 + p * 8;
            const uint32_t parity = (i / NBUF) & 1;
            uint32_t done;
            asm volatile(
                "{\n\t.reg .pred q;\n\t"
                "mbarrier.try_wait.parity.acquire.cta.shared::cta.b64 q, [%1], %2;\n\t"
                "selp.b32 %0, 1, 0, q;\n\t}"
                : "=r"(done) : "r"(mb), "r"(parity) : "memory");
            if (!done) {
                asm volatile(
                    "{\n\t.reg .pred P1;\n\t"
                    "WL_%=:\n\t"
                    "mbarrier.try_wait.parity.acquire.cta.shared::cta.b64 P1, [%0], %1, 0x989680;\n\t"
                    "@P1 bra.uni WD_%=;\n\t"
                    "bra.uni WL_%=;\n\t"
                    "WD_%=:\n\t}"
                    :: "r"(mb), "r"(parity) : "memory");
            }
        }

        // Compute: thread owns one 3x12 patch (4 pool blocks) of this tile.
        {
            float* rp = buf + p * TILE_FLOATS + tid * 12;

            float best[4];
            int   bofs[4];                  // code = dr*12 + col
            float v[3][12];
            #pragma unroll
            for (int dr = 0; dr < 3; dr++) {
                float4 a = *reinterpret_cast<const float4*>(rp + dr * W);
                float4 q = *reinterpret_cast<const float4*>(rp + dr * W + 4);
                float4 c = *reinterpret_cast<const float4*>(rp + dr * W + 8);
                v[dr][0]=a.x; v[dr][1]=a.y; v[dr][2]=a.z;  v[dr][3]=a.w;
                v[dr][4]=q.x; v[dr][5]=q.y; v[dr][6]=q.z;  v[dr][7]=q.w;
                v[dr][8]=c.x; v[dr][9]=c.y; v[dr][10]=c.z; v[dr][11]=c.w;
                #pragma unroll
                for (int col = 0; col < 12; col++) {
                    const int blk  = col / 3;
                    const int code = dr * 12 + col;
                    if (dr == 0 && (col % 3) == 0) {
                        best[blk] = v[dr][col]; bofs[blk] = code;
                    } else if (v[dr][col] > best[blk]) {   // first max wins
                        best[blk] = v[dr][col]; bofs[blk] = code;
                    }
                }
            }
            #pragma unroll
            for (int dr = 0; dr < 3; dr++) {
                float t[12];
                #pragma unroll
                for (int col = 0; col < 12; col++) {
                    const int blk  = col / 3;
                    const int code = dr * 12 + col;
                    t[col] = (bofs[blk] == code) ? best[blk] : 0.0f;
                }
                *reinterpret_cast<float4*>(rp + dr * W)     = make_float4(t[0], t[1], t[2], t[3]);
                *reinterpret_cast<float4*>(rp + dr * W + 4) = make_float4(t[4], t[5], t[6], t[7]);
                *reinterpret_cast<float4*>(rp + dr * W + 8) = make_float4(t[8], t[9], t[10], t[11]);
            }
        }
        __syncthreads();   // all STS done before async-proxy store reads smem

        // Commit bulk store of tile i (drains in background).
        if (tid == 0) {
            asm volatile("fence.proxy.async.shared::cta;" ::: "memory");
            asm volatile(
                "{\n\t.reg .b64 pol;\n\t"
                "createpolicy.fractional.L2::evict_first.b64 pol, 1.0;\n\t"
                "cp.async.bulk.global.shared::cta.bulk_group.L2::cache_hint"
                " [%0], [%1], %2, pol;\n\t}"
                :: "l"(out + (t0 + i) * TILE_FLOATS),
                   "r"(s_base + p * TILE_BYTES), "r"((uint32_t)TILE_BYTES)
                : "memory");
            asm volatile("cp.async.bulk.commit_group;" ::: "memory");
        }
    }

    // Smem reads of all pending stores must finish before CTA retires.
    if (tid == 0)
        asm volatile("cp.async.bulk.wait_group.read 0;" ::: "memory");
}

extern "C" void kernel_launch(void* const* d_in, const int* in_sizes, int n_in,
                              void* d_out, int out_size) {
    const float* x = (const float*)d_in[0];
    float* out = (float*)d_out;
    cudaFuncSetAttribute(pooling_nms_kernel,
                         cudaFuncAttributeMaxDynamicSharedMemorySize, SMEM_TOTAL);
    pooling_nms_kernel<<<GRID, NTHREADS, SMEM_TOTAL>>>(x, out);
}